// round 1
// baseline (speedup 1.0000x reference)
#include <cuda_runtime.h>
#include <math.h>

#define HIDDEN 1024
#define INTER  2048
#define NEXP   8
#define NTOK   8192
#define SLOTS  (NTOK * 2)          // 16384
#define SLOTS_PAD (SLOTS + 64)     // room for last-tile overshoot
#define BM 64
#define BN 64
#define BKK 16
#define MAX_TILES (SLOTS / BM + NEXP)  // 264

// ---------------- device scratch (static, no allocations) ----------------
__device__ int   g_cnt2[NEXP];       // slots per expert (top-2 assignments)
__device__ int   g_cnt1[NEXP];       // top-1 counts (aux loss)
__device__ float g_probsum[NEXP];    // sum of softmax probs (aux loss)
__device__ int   g_offset[NEXP + 1];
__device__ int   g_cursor[NEXP];
__device__ int   g_tile_e[MAX_TILES];
__device__ int   g_tile_row[MAX_TILES];
__device__ int   g_ntiles;
__device__ int   g_tok_list[SLOTS_PAD];   // slot -> token
__device__ int   g_slot_of[SLOTS];        // token*2+k -> slot
__device__ float g_topw[SLOTS];           // token*2+k -> normalized weight
__device__ int   g_topi[SLOTS];           // token*2+k -> expert
__device__ float g_hbuf[(size_t)SLOTS_PAD * INTER];   // GEMM1 output (SiLU'd)
__device__ float g_ybuf[(size_t)SLOTS_PAD * HIDDEN];  // GEMM2 output

// ---------------- init: zero counters + pad list (runs every replay) -----
__global__ void init_kernel() {
    int i = blockIdx.x * blockDim.x + threadIdx.x;
    if (i < NEXP) {
        g_cnt1[i] = 0; g_cnt2[i] = 0; g_cursor[i] = 0; g_probsum[i] = 0.f;
    }
    for (int j = i; j < SLOTS_PAD; j += gridDim.x * blockDim.x)
        g_tok_list[j] = 0;
}

// ---------------- router: 1 warp per token ----------------
__global__ void router_kernel(const float* __restrict__ x,
                              const float* __restrict__ wr) {
    int gwarp = (blockIdx.x * blockDim.x + threadIdx.x) >> 5;
    int lane  = threadIdx.x & 31;
    if (gwarp >= NTOK) return;
    const float* xr = x + (size_t)gwarp * HIDDEN;

    float acc[NEXP];
#pragma unroll
    for (int e = 0; e < NEXP; e++) acc[e] = 0.f;

    for (int k = lane; k < HIDDEN; k += 32) {
        float xv = xr[k];
        const float* w = wr + (size_t)k * NEXP;
#pragma unroll
        for (int e = 0; e < NEXP; e++) acc[e] += xv * w[e];
    }
#pragma unroll
    for (int off = 16; off; off >>= 1) {
#pragma unroll
        for (int e = 0; e < NEXP; e++)
            acc[e] += __shfl_xor_sync(0xffffffffu, acc[e], off);
    }
    if (lane != 0) return;

    // softmax
    float mx = acc[0];
#pragma unroll
    for (int e = 1; e < NEXP; e++) mx = fmaxf(mx, acc[e]);
    float p[NEXP], s = 0.f;
#pragma unroll
    for (int e = 0; e < NEXP; e++) { p[e] = expf(acc[e] - mx); s += p[e]; }
    float inv = 1.f / s;
#pragma unroll
    for (int e = 0; e < NEXP; e++) p[e] *= inv;

    // top-2 (tie -> lower index, matching top_k)
    int i0 = 0; float v0 = p[0];
#pragma unroll
    for (int e = 1; e < NEXP; e++) if (p[e] > v0) { v0 = p[e]; i0 = e; }
    int i1 = -1; float v1 = -1.f;
#pragma unroll
    for (int e = 0; e < NEXP; e++) {
        if (e == i0) continue;
        if (p[e] > v1) { v1 = p[e]; i1 = e; }
    }
    float wsum = v0 + v1;
    float w0 = v0 / wsum, w1 = v1 / wsum;

    g_topi[gwarp * 2 + 0] = i0;  g_topw[gwarp * 2 + 0] = w0;
    g_topi[gwarp * 2 + 1] = i1;  g_topw[gwarp * 2 + 1] = w1;

    atomicAdd(&g_cnt1[i0], 1);
    atomicAdd(&g_cnt2[i0], 1);
    atomicAdd(&g_cnt2[i1], 1);
#pragma unroll
    for (int e = 0; e < NEXP; e++) atomicAdd(&g_probsum[e], p[e]);
}

// ---------------- offsets + tile list (serial, tiny) ----------------
__global__ void offsets_kernel() {
    if (threadIdx.x != 0) return;
    int off = 0;
    for (int e = 0; e < NEXP; e++) {
        g_offset[e] = off;
        off += g_cnt2[e];
    }
    g_offset[NEXP] = off;
    int idx = 0;
    for (int e = 0; e < NEXP; e++) {
        int nt = (g_cnt2[e] + BM - 1) / BM;
        int base = g_offset[e];
        for (int t = 0; t < nt; t++) {
            g_tile_e[idx] = e;
            g_tile_row[idx] = base + t * BM;
            idx++;
        }
    }
    g_ntiles = idx;
}

// ---------------- scatter: (token,k) -> slot ----------------
__global__ void scatter_kernel() {
    int i = blockIdx.x * blockDim.x + threadIdx.x;
    if (i >= SLOTS) return;
    int e = g_topi[i];
    int pos = atomicAdd(&g_cursor[e], 1);
    int slot = g_offset[e] + pos;
    g_tok_list[slot] = i >> 1;
    g_slot_of[i] = slot;
}

// ---------------- grouped SIMT SGEMM ----------------
// A rows: gathered (gemm1: x via tok_list) or identity (gemm2: hbuf slots)
// W: [E, K, N] row-major. out: [slot, N]. silu applied if requested.
__global__ __launch_bounds__(256)
void gemm_kernel(const float* __restrict__ A,
                 const float* __restrict__ W,
                 float* __restrict__ out,
                 int K, int N, int useGather, int applySilu) {
    int tile = blockIdx.x;
    if (tile >= g_ntiles) return;
    int e    = g_tile_e[tile];
    int row0 = g_tile_row[tile];
    int mcount = g_offset[e + 1] - row0;
    if (mcount > BM) mcount = BM;
    int n0 = blockIdx.y * BN;

    __shared__ float As[BKK][BM + 4];   // [k][m], padded
    __shared__ float Bs[BKK][BN];       // [k][n]

    const float* Wb = W + (size_t)e * K * N;

    int tid   = threadIdx.x;
    int a_row = tid >> 2;            // 0..63
    int a_c4  = (tid & 3) * 4;       // 0,4,8,12
    int b_row = tid >> 4;            // 0..15
    int b_c4  = (tid & 15) * 4;      // 0..60
    int tx = tid & 15, ty = tid >> 4;

    int grow = row0 + a_row;
    int srcrow = useGather ? g_tok_list[grow] : grow;
    const float* aptr = A + (size_t)srcrow * K;

    float acc[4][4];
#pragma unroll
    for (int i = 0; i < 4; i++)
#pragma unroll
        for (int j = 0; j < 4; j++) acc[i][j] = 0.f;

    for (int k0 = 0; k0 < K; k0 += BKK) {
        float4 av = *(const float4*)(aptr + k0 + a_c4);
        float4 bv = *(const float4*)(Wb + (size_t)(k0 + b_row) * N + n0 + b_c4);
        __syncthreads();
        As[a_c4 + 0][a_row] = av.x;
        As[a_c4 + 1][a_row] = av.y;
        As[a_c4 + 2][a_row] = av.z;
        As[a_c4 + 3][a_row] = av.w;
        *(float4*)&Bs[b_row][b_c4] = bv;
        __syncthreads();
#pragma unroll
        for (int kk = 0; kk < BKK; kk++) {
            float4 a = *(const float4*)&As[kk][ty * 4];
            float4 b = *(const float4*)&Bs[kk][tx * 4];
            acc[0][0] += a.x * b.x; acc[0][1] += a.x * b.y; acc[0][2] += a.x * b.z; acc[0][3] += a.x * b.w;
            acc[1][0] += a.y * b.x; acc[1][1] += a.y * b.y; acc[1][2] += a.y * b.z; acc[1][3] += a.y * b.w;
            acc[2][0] += a.z * b.x; acc[2][1] += a.z * b.y; acc[2][2] += a.z * b.z; acc[2][3] += a.z * b.w;
            acc[3][0] += a.w * b.x; acc[3][1] += a.w * b.y; acc[3][2] += a.w * b.z; acc[3][3] += a.w * b.w;
        }
    }

#pragma unroll
    for (int i = 0; i < 4; i++) {
        int r = ty * 4 + i;
        if (r < mcount) {
            float4 v;
            v.x = acc[i][0]; v.y = acc[i][1]; v.z = acc[i][2]; v.w = acc[i][3];
            if (applySilu) {
                v.x = v.x / (1.f + expf(-v.x));
                v.y = v.y / (1.f + expf(-v.y));
                v.z = v.z / (1.f + expf(-v.z));
                v.w = v.w / (1.f + expf(-v.w));
            }
            *(float4*)(out + (size_t)(row0 + r) * N + n0 + tx * 4) = v;
        }
    }
}

// ---------------- combine: out[t] = w0*y[slot0] + w1*y[slot1] ----------
__global__ void combine_kernel(float* __restrict__ out) {
    int token = blockIdx.x;
    int tid = threadIdx.x;
    int s0 = g_slot_of[token * 2 + 0];
    int s1 = g_slot_of[token * 2 + 1];
    float w0 = g_topw[token * 2 + 0];
    float w1 = g_topw[token * 2 + 1];
    const float4* y0 = (const float4*)(g_ybuf + (size_t)s0 * HIDDEN);
    const float4* y1 = (const float4*)(g_ybuf + (size_t)s1 * HIDDEN);
    float4* o = (float4*)(out + (size_t)token * HIDDEN);
    for (int h = tid; h < HIDDEN / 4; h += blockDim.x) {
        float4 a = y0[h], b = y1[h], r;
        r.x = w0 * a.x + w1 * b.x;
        r.y = w0 * a.y + w1 * b.y;
        r.z = w0 * a.z + w1 * b.z;
        r.w = w0 * a.w + w1 * b.w;
        o[h] = r;
    }
}

// ---------------- aux loss ----------------
__global__ void aux_kernel(float* __restrict__ out, int out_size) {
    if (threadIdx.x != 0 || blockIdx.x != 0) return;
    if (out_size <= NTOK * HIDDEN) return;
    float aux = 0.f;
    for (int e = 0; e < NEXP; e++)
        aux += ((float)g_cnt1[e] / (float)NTOK) * (g_probsum[e] / (float)NTOK);
    aux *= (float)NEXP;
    out[out_size - 1] = aux;
}

// ---------------- launch ----------------
extern "C" void kernel_launch(void* const* d_in, const int* in_sizes, int n_in,
                              void* d_out, int out_size) {
    const float* x  = (const float*)d_in[0];
    const float* wr = (const float*)d_in[1];
    const float* w1 = (const float*)d_in[2];
    const float* w2 = (const float*)d_in[3];
    float* out = (float*)d_out;

    float* hbuf; cudaGetSymbolAddress((void**)&hbuf, g_hbuf);
    float* ybuf; cudaGetSymbolAddress((void**)&ybuf, g_ybuf);

    init_kernel<<<64, 256>>>();
    router_kernel<<<(NTOK * 32 + 255) / 256, 256>>>(x, wr);
    offsets_kernel<<<1, 32>>>();
    scatter_kernel<<<(SLOTS + 255) / 256, 256>>>();

    // GEMM1: [slots, INTER] = gather(x) @ W1[e], SiLU
    gemm_kernel<<<dim3(MAX_TILES, INTER / BN), 256>>>(
        x, w1, hbuf, HIDDEN, INTER, /*gather=*/1, /*silu=*/1);
    // GEMM2: [slots, HIDDEN] = hbuf @ W2[e]
    gemm_kernel<<<dim3(MAX_TILES, HIDDEN / BN), 256>>>(
        hbuf, w2, ybuf, INTER, HIDDEN, /*gather=*/0, /*silu=*/0);

    combine_kernel<<<NTOK, 256>>>(out);
    aux_kernel<<<1, 32>>>(out, out_size);
}

// round 3
// speedup vs baseline: 2.2758x; 2.2758x over previous
#include <cuda_runtime.h>
#include <cuda_bf16.h>
#include <math.h>
#include <stdint.h>

#define HIDDEN 1024
#define INTER  2048
#define NEXP   8
#define NTOK   8192
#define SLOTS  (NTOK * 2)          // 16384
#define BM 128
#define BN 128
#define BK 32
#define SLOTS_PAD (SLOTS + BM)
#define MAX_TILES (SLOTS / BM + NEXP)  // 136

#define STRIDE 80                  // padded smem row bytes (32 bf16 = 64B + 16B pad)
#define TILEBYTES (128 * STRIDE)   // 10240
#define STAGEBYTES (4 * TILEBYTES) // Ah, Al, Bh, Bl = 40960
#define SMEM_TOTAL (2 * STAGEBYTES)// 81920

// ---------------- device scratch (static, no allocations) ----------------
__device__ int   g_cnt2[NEXP];
__device__ int   g_cnt1[NEXP];
__device__ float g_probsum[NEXP];
__device__ int   g_offset[NEXP + 1];
__device__ int   g_cursor[NEXP];
__device__ int   g_tile_e[MAX_TILES];
__device__ int   g_tile_row[MAX_TILES];
__device__ int   g_ntiles;
__device__ int   g_tok_list[SLOTS_PAD];
__device__ int   g_slot_of[SLOTS];
__device__ float g_topw[SLOTS];
__device__ int   g_topi[SLOTS];

__device__ __nv_bfloat16 g_x_hi[NTOK * HIDDEN];
__device__ __nv_bfloat16 g_x_lo[NTOK * HIDDEN];
// W transposed to [E][N][K] K-major, split hi/lo
__device__ __nv_bfloat16 g_w1t_hi[NEXP * INTER * HIDDEN];
__device__ __nv_bfloat16 g_w1t_lo[NEXP * INTER * HIDDEN];
__device__ __nv_bfloat16 g_w2t_hi[NEXP * HIDDEN * INTER];
__device__ __nv_bfloat16 g_w2t_lo[NEXP * HIDDEN * INTER];
// GEMM1 output (post-SiLU), pre-split for GEMM2
__device__ __nv_bfloat16 g_hb_hi[(size_t)SLOTS_PAD * INTER];
__device__ __nv_bfloat16 g_hb_lo[(size_t)SLOTS_PAD * INTER];
__device__ float g_ybuf[(size_t)SLOTS_PAD * HIDDEN];

// ---------------- PTX helpers ----------------
__device__ __forceinline__ uint32_t smem_u32(const void* p) {
    uint32_t a;
    asm("{ .reg .u64 t; cvta.to.shared.u64 t, %1; cvt.u32.u64 %0, t; }" : "=r"(a) : "l"(p));
    return a;
}
#define CP_ASYNC16(dst, src) \
    asm volatile("cp.async.cg.shared.global [%0], [%1], 16;" :: "r"(dst), "l"(src) : "memory")
#define CP_COMMIT() asm volatile("cp.async.commit_group;" ::: "memory")
#define CP_WAIT(n)  asm volatile("cp.async.wait_group %0;" :: "n"(n) : "memory")

#define LDSM_X4(r, a) \
    asm volatile("ldmatrix.sync.aligned.m8n8.x4.shared.b16 {%0,%1,%2,%3}, [%4];" \
        : "=r"((r)[0]), "=r"((r)[1]), "=r"((r)[2]), "=r"((r)[3]) : "r"(a))

#define MMA16816(c, a, b0, b1) \
    asm volatile("mma.sync.aligned.m16n8k16.row.col.f32.bf16.bf16.f32 " \
        "{%0,%1,%2,%3}, {%4,%5,%6,%7}, {%8,%9}, {%0,%1,%2,%3};" \
        : "+f"((c)[0]), "+f"((c)[1]), "+f"((c)[2]), "+f"((c)[3]) \
        : "r"((a)[0]), "r"((a)[1]), "r"((a)[2]), "r"((a)[3]), "r"(b0), "r"(b1))

// ---------------- init ----------------
__global__ void init_kernel() {
    int i = blockIdx.x * blockDim.x + threadIdx.x;
    if (i < NEXP) { g_cnt1[i] = 0; g_cnt2[i] = 0; g_cursor[i] = 0; g_probsum[i] = 0.f; }
    for (int j = i; j < SLOTS_PAD; j += gridDim.x * blockDim.x) g_tok_list[j] = 0;
}

// ---------------- router: 1 warp per token ----------------
__global__ void router_kernel(const float* __restrict__ x, const float* __restrict__ wr) {
    int gwarp = (blockIdx.x * blockDim.x + threadIdx.x) >> 5;
    int lane = threadIdx.x & 31;
    if (gwarp >= NTOK) return;
    const float* xr = x + (size_t)gwarp * HIDDEN;
    float acc[NEXP];
#pragma unroll
    for (int e = 0; e < NEXP; e++) acc[e] = 0.f;
    for (int k = lane; k < HIDDEN; k += 32) {
        float xv = xr[k];
        const float* w = wr + (size_t)k * NEXP;
#pragma unroll
        for (int e = 0; e < NEXP; e++) acc[e] += xv * w[e];
    }
#pragma unroll
    for (int off = 16; off; off >>= 1)
#pragma unroll
        for (int e = 0; e < NEXP; e++) acc[e] += __shfl_xor_sync(0xffffffffu, acc[e], off);
    if (lane != 0) return;

    float mx = acc[0];
#pragma unroll
    for (int e = 1; e < NEXP; e++) mx = fmaxf(mx, acc[e]);
    float p[NEXP], s = 0.f;
#pragma unroll
    for (int e = 0; e < NEXP; e++) { p[e] = expf(acc[e] - mx); s += p[e]; }
    float inv = 1.f / s;
#pragma unroll
    for (int e = 0; e < NEXP; e++) p[e] *= inv;

    int i0 = 0; float v0 = p[0];
#pragma unroll
    for (int e = 1; e < NEXP; e++) if (p[e] > v0) { v0 = p[e]; i0 = e; }
    int i1 = -1; float v1 = -1.f;
#pragma unroll
    for (int e = 0; e < NEXP; e++) { if (e == i0) continue; if (p[e] > v1) { v1 = p[e]; i1 = e; } }
    float wsum = v0 + v1;
    g_topi[gwarp * 2 + 0] = i0; g_topw[gwarp * 2 + 0] = v0 / wsum;
    g_topi[gwarp * 2 + 1] = i1; g_topw[gwarp * 2 + 1] = v1 / wsum;
    atomicAdd(&g_cnt1[i0], 1);
    atomicAdd(&g_cnt2[i0], 1);
    atomicAdd(&g_cnt2[i1], 1);
#pragma unroll
    for (int e = 0; e < NEXP; e++) atomicAdd(&g_probsum[e], p[e]);
}

// ---------------- offsets + tile list ----------------
__global__ void offsets_kernel() {
    if (threadIdx.x != 0) return;
    int off = 0;
    for (int e = 0; e < NEXP; e++) { g_offset[e] = off; off += g_cnt2[e]; }
    g_offset[NEXP] = off;
    int idx = 0;
    for (int e = 0; e < NEXP; e++) {
        int nt = (g_cnt2[e] + BM - 1) / BM;
        int base = g_offset[e];
        for (int t = 0; t < nt; t++) { g_tile_e[idx] = e; g_tile_row[idx] = base + t * BM; idx++; }
    }
    g_ntiles = idx;
}

// ---------------- scatter ----------------
__global__ void scatter_kernel() {
    int i = blockIdx.x * blockDim.x + threadIdx.x;
    if (i >= SLOTS) return;
    int e = g_topi[i];
    int pos = atomicAdd(&g_cursor[e], 1);
    int slot = g_offset[e] + pos;
    g_tok_list[slot] = i >> 1;
    g_slot_of[i] = slot;
}

// ---------------- x split ----------------
__global__ void split_x_kernel(const float* __restrict__ x) {
    int i = blockIdx.x * blockDim.x + threadIdx.x;
    if (i >= NTOK * HIDDEN) return;
    float v = x[i];
    __nv_bfloat16 h = __float2bfloat16(v);
    g_x_hi[i] = h;
    g_x_lo[i] = __float2bfloat16(v - __bfloat162float(h));
}

// ---------------- W transpose + split: [E][K][N] f32 -> [E][N][K] bf16 hi/lo ----
__global__ void wsplit_kernel(const float* __restrict__ W,
                              __nv_bfloat16* __restrict__ hi,
                              __nv_bfloat16* __restrict__ lo,
                              int K, int N) {
    __shared__ float t[32][33];
    int e = blockIdx.z;
    const float* Wb = W + (size_t)e * K * N;
    int n0 = blockIdx.x * 32, k0 = blockIdx.y * 32;
    for (int i = threadIdx.y; i < 32; i += 8)
        t[i][threadIdx.x] = Wb[(size_t)(k0 + i) * N + n0 + threadIdx.x];
    __syncthreads();
    for (int i = threadIdx.y; i < 32; i += 8) {
        float v = t[threadIdx.x][i];           // (k=k0+tx, n=n0+i)
        __nv_bfloat16 h = __float2bfloat16(v);
        size_t idx = ((size_t)e * N + n0 + i) * K + k0 + threadIdx.x;
        hi[idx] = h;
        lo[idx] = __float2bfloat16(v - __bfloat162float(h));
    }
}

// ---------------- grouped bf16-split mma.sync GEMM ----------------
// D[BM x BN] = split(A) @ split(B)^T;  B stored [E][N][K] K-major.
__global__ __launch_bounds__(256, 1)
void moe_gemm(const __nv_bfloat16* __restrict__ Ahi, const __nv_bfloat16* __restrict__ Alo,
              const __nv_bfloat16* __restrict__ Bhi, const __nv_bfloat16* __restrict__ Blo,
              int K, int Nd, int useGather, int applySilu,
              __nv_bfloat16* __restrict__ outHi, __nv_bfloat16* __restrict__ outLo,
              float* __restrict__ outF) {
    int tile = blockIdx.x;
    if (tile >= g_ntiles) return;
    int e = g_tile_e[tile];
    int row0 = g_tile_row[tile];
    int mcount = g_offset[e + 1] - row0;
    if (mcount > BM) mcount = BM;
    int n0 = blockIdx.y * BN;

    extern __shared__ char smem[];
    uint32_t sb = smem_u32(smem);
    int tid = threadIdx.x;
    int lane = tid & 31;
    int wid = tid >> 5;
    int warp_m = wid & 1;        // 0..1 -> 64 rows each
    int warp_n = wid >> 1;       // 0..3 -> 32 cols each

    // ---- cp.async source/dest offsets (2 16B chunks per operand per thread) ----
    uint32_t a_src[2], a_dst[2], b_src[2], b_dst[2];
#pragma unroll
    for (int i = 0; i < 2; i++) {
        int id = tid + i * 256;
        int row = id >> 2, c16 = id & 3;
        int srow = useGather ? g_tok_list[row0 + row] : (row0 + row);
        a_src[i] = (uint32_t)srow * (uint32_t)K + c16 * 8;
        a_dst[i] = row * STRIDE + c16 * 16;
        b_src[i] = ((uint32_t)e * (uint32_t)Nd + n0 + row) * (uint32_t)K + c16 * 8;
        b_dst[i] = a_dst[i];
    }

    float acc[4][4][4];
#pragma unroll
    for (int m = 0; m < 4; m++)
#pragma unroll
        for (int n = 0; n < 4; n++)
#pragma unroll
            for (int r = 0; r < 4; r++) acc[m][n][r] = 0.f;

    // ldmatrix smem-relative offsets
    uint32_t a_rel[4], b_rel[2];
    {
        int row_a = warp_m * 64 + (lane & 15);
        int ka = ((lane >> 4) << 3) * 2;            // 0 or 16 bytes
#pragma unroll
        for (int m = 0; m < 4; m++) a_rel[m] = (row_a + m * 16) * STRIDE + ka;
        int row_b = warp_n * 32 + (lane & 7) + ((lane & 16) >> 1);
        int kb = (lane & 8) * 2;                    // 0 or 16 bytes
#pragma unroll
        for (int p = 0; p < 2; p++) b_rel[p] = (row_b + p * 16) * STRIDE + kb;
    }

    int nch = K / BK;
    // prologue
    {
        uint32_t base = sb;
#pragma unroll
        for (int i = 0; i < 2; i++) {
            CP_ASYNC16(base + a_dst[i],                  (const char*)(Ahi + a_src[i]));
            CP_ASYNC16(base + TILEBYTES + a_dst[i],      (const char*)(Alo + a_src[i]));
            CP_ASYNC16(base + 2 * TILEBYTES + b_dst[i],  (const char*)(Bhi + b_src[i]));
            CP_ASYNC16(base + 3 * TILEBYTES + b_dst[i],  (const char*)(Blo + b_src[i]));
        }
        CP_COMMIT();
    }

    for (int ch = 0; ch < nch; ch++) {
        int cur = ch & 1;
        if (ch + 1 < nch) {
            uint32_t base = sb + (cur ^ 1) * STAGEBYTES;
            uint32_t k0 = (ch + 1) * BK;
#pragma unroll
            for (int i = 0; i < 2; i++) {
                CP_ASYNC16(base + a_dst[i],                 (const char*)(Ahi + a_src[i] + k0));
                CP_ASYNC16(base + TILEBYTES + a_dst[i],     (const char*)(Alo + a_src[i] + k0));
                CP_ASYNC16(base + 2 * TILEBYTES + b_dst[i], (const char*)(Bhi + b_src[i] + k0));
                CP_ASYNC16(base + 3 * TILEBYTES + b_dst[i], (const char*)(Blo + b_src[i] + k0));
            }
            CP_COMMIT();
            CP_WAIT(1);
        } else {
            CP_WAIT(0);
        }
        __syncthreads();

        uint32_t Ahb = sb + cur * STAGEBYTES;
        uint32_t Alb = Ahb + TILEBYTES;
        uint32_t Bhb = Ahb + 2 * TILEBYTES;
        uint32_t Blb = Ahb + 3 * TILEBYTES;

#pragma unroll
        for (int ks = 0; ks < 2; ks++) {
            uint32_t kb = ks * 32;  // 16 bf16 = 32 bytes
            uint32_t Ah[4][4], Al[4][4], Bh[2][4], Bl[2][4];
#pragma unroll
            for (int m = 0; m < 4; m++) {
                LDSM_X4(Ah[m], Ahb + a_rel[m] + kb);
                LDSM_X4(Al[m], Alb + a_rel[m] + kb);
            }
#pragma unroll
            for (int p = 0; p < 2; p++) {
                LDSM_X4(Bh[p], Bhb + b_rel[p] + kb);
                LDSM_X4(Bl[p], Blb + b_rel[p] + kb);
            }
#pragma unroll
            for (int n = 0; n < 4; n++) {
                int p = n >> 1, q = (n & 1) * 2;
                uint32_t bh0 = Bh[p][q], bh1 = Bh[p][q + 1];
                uint32_t bl0 = Bl[p][q], bl1 = Bl[p][q + 1];
#pragma unroll
                for (int m = 0; m < 4; m++) {
                    MMA16816(acc[m][n], Ah[m], bh0, bh1);
                    MMA16816(acc[m][n], Ah[m], bl0, bl1);
                    MMA16816(acc[m][n], Al[m], bh0, bh1);
                }
            }
        }
        __syncthreads();
    }

    // ---- epilogue ----
    int g = lane >> 2, tig = lane & 3;
#pragma unroll
    for (int m = 0; m < 4; m++) {
        int lr = warp_m * 64 + m * 16 + g;
#pragma unroll
        for (int n = 0; n < 4; n++) {
            int col = n0 + warp_n * 32 + n * 8 + 2 * tig;
            float* c = acc[m][n];
#pragma unroll
            for (int h = 0; h < 2; h++) {
                int lrow = lr + h * 8;
                if (lrow >= mcount) continue;
                size_t grow = (size_t)(row0 + lrow);
                float f0 = c[h * 2 + 0], f1 = c[h * 2 + 1];
                if (applySilu) {
                    f0 = f0 / (1.f + expf(-f0));
                    f1 = f1 / (1.f + expf(-f1));
                    __nv_bfloat16 h0 = __float2bfloat16(f0);
                    __nv_bfloat16 h1 = __float2bfloat16(f1);
                    __nv_bfloat162 hv; hv.x = h0; hv.y = h1;
                    __nv_bfloat162 lv;
                    lv.x = __float2bfloat16(f0 - __bfloat162float(h0));
                    lv.y = __float2bfloat16(f1 - __bfloat162float(h1));
                    size_t idx = grow * Nd + col;
                    *reinterpret_cast<__nv_bfloat162*>(outHi + idx) = hv;
                    *reinterpret_cast<__nv_bfloat162*>(outLo + idx) = lv;
                } else {
                    float2 v; v.x = f0; v.y = f1;
                    *reinterpret_cast<float2*>(outF + grow * Nd + col) = v;
                }
            }
        }
    }
}

// ---------------- combine ----------------
__global__ void combine_kernel(float* __restrict__ out) {
    int token = blockIdx.x;
    int tid = threadIdx.x;
    int s0 = g_slot_of[token * 2 + 0];
    int s1 = g_slot_of[token * 2 + 1];
    float w0 = g_topw[token * 2 + 0];
    float w1 = g_topw[token * 2 + 1];
    const float4* y0 = (const float4*)(g_ybuf + (size_t)s0 * HIDDEN);
    const float4* y1 = (const float4*)(g_ybuf + (size_t)s1 * HIDDEN);
    float4* o = (float4*)(out + (size_t)token * HIDDEN);
    for (int h = tid; h < HIDDEN / 4; h += blockDim.x) {
        float4 a = y0[h], b = y1[h], r;
        r.x = w0 * a.x + w1 * b.x;
        r.y = w0 * a.y + w1 * b.y;
        r.z = w0 * a.z + w1 * b.z;
        r.w = w0 * a.w + w1 * b.w;
        o[h] = r;
    }
}

// ---------------- aux loss ----------------
__global__ void aux_kernel(float* __restrict__ out, int out_size) {
    if (threadIdx.x != 0 || blockIdx.x != 0) return;
    if (out_size <= NTOK * HIDDEN) return;
    float aux = 0.f;
    for (int e = 0; e < NEXP; e++)
        aux += ((float)g_cnt1[e] / (float)NTOK) * (g_probsum[e] / (float)NTOK);
    out[out_size - 1] = aux * (float)NEXP;
}

// ---------------- launch ----------------
extern "C" void kernel_launch(void* const* d_in, const int* in_sizes, int n_in,
                              void* d_out, int out_size) {
    const float* x  = (const float*)d_in[0];
    const float* wr = (const float*)d_in[1];
    const float* w1 = (const float*)d_in[2];
    const float* w2 = (const float*)d_in[3];
    float* out = (float*)d_out;

    static int configured = 0;
    if (!configured) {
        cudaFuncSetAttribute(moe_gemm, cudaFuncAttributeMaxDynamicSharedMemorySize, SMEM_TOTAL);
        configured = 1;
    }

    __nv_bfloat16 *xh, *xl, *w1h, *w1l, *w2h, *w2l, *hbh, *hbl;
    float* ybuf;
    cudaGetSymbolAddress((void**)&xh,  g_x_hi);
    cudaGetSymbolAddress((void**)&xl,  g_x_lo);
    cudaGetSymbolAddress((void**)&w1h, g_w1t_hi);
    cudaGetSymbolAddress((void**)&w1l, g_w1t_lo);
    cudaGetSymbolAddress((void**)&w2h, g_w2t_hi);
    cudaGetSymbolAddress((void**)&w2l, g_w2t_lo);
    cudaGetSymbolAddress((void**)&hbh, g_hb_hi);
    cudaGetSymbolAddress((void**)&hbl, g_hb_lo);
    cudaGetSymbolAddress((void**)&ybuf, g_ybuf);

    init_kernel<<<64, 256>>>();
    router_kernel<<<(NTOK * 32 + 255) / 256, 256>>>(x, wr);
    offsets_kernel<<<1, 32>>>();
    scatter_kernel<<<(SLOTS + 255) / 256, 256>>>();

    split_x_kernel<<<(NTOK * HIDDEN + 255) / 256, 256>>>(x);
    wsplit_kernel<<<dim3(INTER / 32, HIDDEN / 32, NEXP), dim3(32, 8)>>>(w1, w1h, w1l, HIDDEN, INTER);
    wsplit_kernel<<<dim3(HIDDEN / 32, INTER / 32, NEXP), dim3(32, 8)>>>(w2, w2h, w2l, INTER, HIDDEN);

    // GEMM1: hb[slot, INTER] = silu(gather(x) @ W1), split bf16
    moe_gemm<<<dim3(MAX_TILES, INTER / BN), 256, SMEM_TOTAL>>>(
        xh, xl, w1h, w1l, HIDDEN, INTER, 1, 1, hbh, hbl, (float*)0);
    // GEMM2: ybuf[slot, HIDDEN] = hb @ W2
    moe_gemm<<<dim3(MAX_TILES, HIDDEN / BN), 256, SMEM_TOTAL>>>(
        hbh, hbl, w2h, w2l, INTER, HIDDEN, 0, 0, (__nv_bfloat16*)0, (__nv_bfloat16*)0, ybuf);

    combine_kernel<<<NTOK, 256>>>(out);
    aux_kernel<<<1, 32>>>(out, out_size);
}

// round 5
// speedup vs baseline: 3.3963x; 1.4923x over previous
#include <cuda_runtime.h>
#include <cuda_fp16.h>
#include <math.h>
#include <stdint.h>

#define HIDDEN 1024
#define INTER  2048
#define NEXP   8
#define NTOK   8192
#define SLOTS  (NTOK * 2)          // 16384
#define BM 128
#define BN 128
#define BK 32
#define SLOTS_PAD (SLOTS + BM)
#define MAX_TILES (SLOTS / BM + NEXP)  // 136

#define STRIDE 80                  // padded smem row bytes (32 fp16 = 64B + 16B pad)
#define TILEBYTES (128 * STRIDE)   // 10240
#define STAGEBYTES (3 * TILEBYTES) // Ah, Al, B = 30720
#define NSTAGE 3
#define SMEM_TOTAL (NSTAGE * STAGEBYTES)  // 92160

// ---------------- device scratch (static, no allocations) ----------------
__device__ int   g_cnt2[NEXP];
__device__ int   g_cnt1[NEXP];
__device__ float g_probsum[NEXP];
__device__ int   g_offset[NEXP + 1];
__device__ int   g_cursor[NEXP];
__device__ int   g_tile_e[MAX_TILES];
__device__ int   g_tile_row[MAX_TILES];
__device__ int   g_ntiles;
__device__ int   g_tok_list[SLOTS_PAD];
__device__ int   g_slot_of[SLOTS];
__device__ float g_topw[SLOTS];
__device__ int   g_topi[SLOTS];

__device__ __half g_x_hi[NTOK * HIDDEN];
__device__ __half g_x_lo[NTOK * HIDDEN];
// W transposed to [E][N][K] K-major, single fp16
__device__ __half g_w1t[NEXP * INTER * HIDDEN];
__device__ __half g_w2t[NEXP * HIDDEN * INTER];
// GEMM1 output (post-SiLU), fp16 hi/lo for GEMM2's A
__device__ __half g_hb_hi[(size_t)SLOTS_PAD * INTER];
__device__ __half g_hb_lo[(size_t)SLOTS_PAD * INTER];
__device__ float g_ybuf[(size_t)SLOTS_PAD * HIDDEN];

// ---------------- PTX helpers ----------------
__device__ __forceinline__ uint32_t smem_u32(const void* p) {
    uint32_t a;
    asm("{ .reg .u64 t; cvta.to.shared.u64 t, %1; cvt.u32.u64 %0, t; }" : "=r"(a) : "l"(p));
    return a;
}
#define CP_ASYNC16(dst, src) \
    asm volatile("cp.async.cg.shared.global [%0], [%1], 16;" :: "r"(dst), "l"(src) : "memory")
#define CP_COMMIT() asm volatile("cp.async.commit_group;" ::: "memory")
#define CP_WAIT(n)  asm volatile("cp.async.wait_group %0;" :: "n"(n) : "memory")

#define LDSM_X4(r, a) \
    asm volatile("ldmatrix.sync.aligned.m8n8.x4.shared.b16 {%0,%1,%2,%3}, [%4];" \
        : "=r"((r)[0]), "=r"((r)[1]), "=r"((r)[2]), "=r"((r)[3]) : "r"(a))

#define MMA16816(c, a, b0, b1) \
    asm volatile("mma.sync.aligned.m16n8k16.row.col.f32.f16.f16.f32 " \
        "{%0,%1,%2,%3}, {%4,%5,%6,%7}, {%8,%9}, {%0,%1,%2,%3};" \
        : "+f"((c)[0]), "+f"((c)[1]), "+f"((c)[2]), "+f"((c)[3]) \
        : "r"((a)[0]), "r"((a)[1]), "r"((a)[2]), "r"((a)[3]), "r"(b0), "r"(b1))

// ---------------- init ----------------
__global__ void init_kernel() {
    int i = blockIdx.x * blockDim.x + threadIdx.x;
    if (i < NEXP) { g_cnt1[i] = 0; g_cnt2[i] = 0; g_cursor[i] = 0; g_probsum[i] = 0.f; }
    for (int j = i; j < SLOTS_PAD; j += gridDim.x * blockDim.x) g_tok_list[j] = 0;
}

// ---------------- router: 1 warp per token ----------------
__global__ void router_kernel(const float* __restrict__ x, const float* __restrict__ wr) {
    int gwarp = (blockIdx.x * blockDim.x + threadIdx.x) >> 5;
    int lane = threadIdx.x & 31;
    if (gwarp >= NTOK) return;
    const float* xr = x + (size_t)gwarp * HIDDEN;
    float acc[NEXP];
#pragma unroll
    for (int e = 0; e < NEXP; e++) acc[e] = 0.f;
    for (int k = lane; k < HIDDEN; k += 32) {
        float xv = xr[k];
        const float* w = wr + (size_t)k * NEXP;
#pragma unroll
        for (int e = 0; e < NEXP; e++) acc[e] += xv * w[e];
    }
#pragma unroll
    for (int off = 16; off; off >>= 1)
#pragma unroll
        for (int e = 0; e < NEXP; e++) acc[e] += __shfl_xor_sync(0xffffffffu, acc[e], off);
    if (lane != 0) return;

    float mx = acc[0];
#pragma unroll
    for (int e = 1; e < NEXP; e++) mx = fmaxf(mx, acc[e]);
    float p[NEXP], s = 0.f;
#pragma unroll
    for (int e = 0; e < NEXP; e++) { p[e] = expf(acc[e] - mx); s += p[e]; }
    float inv = 1.f / s;
#pragma unroll
    for (int e = 0; e < NEXP; e++) p[e] *= inv;

    int i0 = 0; float v0 = p[0];
#pragma unroll
    for (int e = 1; e < NEXP; e++) if (p[e] > v0) { v0 = p[e]; i0 = e; }
    int i1 = -1; float v1 = -1.f;
#pragma unroll
    for (int e = 0; e < NEXP; e++) { if (e == i0) continue; if (p[e] > v1) { v1 = p[e]; i1 = e; } }
    float wsum = v0 + v1;
    g_topi[gwarp * 2 + 0] = i0; g_topw[gwarp * 2 + 0] = v0 / wsum;
    g_topi[gwarp * 2 + 1] = i1; g_topw[gwarp * 2 + 1] = v1 / wsum;
    atomicAdd(&g_cnt1[i0], 1);
    atomicAdd(&g_cnt2[i0], 1);
    atomicAdd(&g_cnt2[i1], 1);
#pragma unroll
    for (int e = 0; e < NEXP; e++) atomicAdd(&g_probsum[e], p[e]);
}

// ---------------- offsets + tile list ----------------
__global__ void offsets_kernel() {
    if (threadIdx.x != 0) return;
    int off = 0;
    for (int e = 0; e < NEXP; e++) { g_offset[e] = off; off += g_cnt2[e]; }
    g_offset[NEXP] = off;
    int idx = 0;
    for (int e = 0; e < NEXP; e++) {
        int nt = (g_cnt2[e] + BM - 1) / BM;
        int base = g_offset[e];
        for (int t = 0; t < nt; t++) { g_tile_e[idx] = e; g_tile_row[idx] = base + t * BM; idx++; }
    }
    g_ntiles = idx;
}

// ---------------- scatter ----------------
__global__ void scatter_kernel() {
    int i = blockIdx.x * blockDim.x + threadIdx.x;
    if (i >= SLOTS) return;
    int e = g_topi[i];
    int pos = atomicAdd(&g_cursor[e], 1);
    int slot = g_offset[e] + pos;
    g_tok_list[slot] = i >> 1;
    g_slot_of[i] = slot;
}

// ---------------- x split: f32 -> fp16 hi + fp16 lo ----------------
__global__ void split_x_kernel(const float* __restrict__ x) {
    int i = blockIdx.x * blockDim.x + threadIdx.x;
    if (i >= NTOK * HIDDEN) return;
    float v = x[i];
    __half h = __float2half(v);
    g_x_hi[i] = h;
    g_x_lo[i] = __float2half(v - __half2float(h));
}

// ---------------- W transpose + convert: [E][K][N] f32 -> [E][N][K] fp16 ----
__global__ void wconv_kernel(const float* __restrict__ W,
                             __half* __restrict__ out,
                             int K, int N) {
    __shared__ float t[32][33];
    int e = blockIdx.z;
    const float* Wb = W + (size_t)e * K * N;
    int n0 = blockIdx.x * 32, k0 = blockIdx.y * 32;
    for (int i = threadIdx.y; i < 32; i += 8)
        t[i][threadIdx.x] = Wb[(size_t)(k0 + i) * N + n0 + threadIdx.x];
    __syncthreads();
    for (int i = threadIdx.y; i < 32; i += 8) {
        float v = t[threadIdx.x][i];           // (k=k0+tx, n=n0+i)
        out[((size_t)e * N + n0 + i) * K + k0 + threadIdx.x] = __float2half(v);
    }
}

// ---------------- grouped fp16 split-A mma.sync GEMM ----------------
// D[BM x BN] = (Ah + Al) @ B^T, B stored [E][N][K] K-major fp16.
__global__ __launch_bounds__(256, 2)
void moe_gemm(const __half* __restrict__ Ahi, const __half* __restrict__ Alo,
              const __half* __restrict__ Bw,
              int K, int Nd, int useGather, int applySilu,
              __half* __restrict__ outHi, __half* __restrict__ outLo,
              float* __restrict__ outF) {
    int tile = blockIdx.x;
    if (tile >= g_ntiles) return;
    int e = g_tile_e[tile];
    int row0 = g_tile_row[tile];
    int mcount = g_offset[e + 1] - row0;
    if (mcount > BM) mcount = BM;
    int n0 = blockIdx.y * BN;

    extern __shared__ char smem[];
    uint32_t sb = smem_u32(smem);
    int tid = threadIdx.x;
    int lane = tid & 31;
    int wid = tid >> 5;
    int warp_m = wid & 1;        // 0..1 -> 64 rows each
    int warp_n = wid >> 1;       // 0..3 -> 32 cols each

    // ---- cp.async source/dest offsets (2 16B chunks per operand per thread) ----
    uint32_t a_src[2], a_dst[2], b_src[2];
#pragma unroll
    for (int i = 0; i < 2; i++) {
        int id = tid + i * 256;
        int row = id >> 2, c16 = id & 3;
        int srow = useGather ? g_tok_list[row0 + row] : (row0 + row);
        a_src[i] = (uint32_t)srow * (uint32_t)K + c16 * 8;
        a_dst[i] = row * STRIDE + c16 * 16;
        b_src[i] = ((uint32_t)e * (uint32_t)Nd + n0 + row) * (uint32_t)K + c16 * 8;
    }

    float acc[4][4][4];
#pragma unroll
    for (int m = 0; m < 4; m++)
#pragma unroll
        for (int n = 0; n < 4; n++)
#pragma unroll
            for (int r = 0; r < 4; r++) acc[m][n][r] = 0.f;

    // ldmatrix smem-relative offsets
    uint32_t a_rel[4], b_rel[2];
    {
        int row_a = warp_m * 64 + (lane & 15);
        int ka = ((lane >> 4) << 3) * 2;            // 0 or 16 bytes
#pragma unroll
        for (int m = 0; m < 4; m++) a_rel[m] = (row_a + m * 16) * STRIDE + ka;
        int row_b = warp_n * 32 + (lane & 7) + ((lane & 16) >> 1);
        int kb = (lane & 8) * 2;                    // 0 or 16 bytes
#pragma unroll
        for (int p = 0; p < 2; p++) b_rel[p] = (row_b + p * 16) * STRIDE + kb;
    }

    int nch = K / BK;

    // prologue: stages 0 and 1, each its own commit group
#pragma unroll
    for (int ps = 0; ps < 2; ps++) {
        uint32_t base = sb + ps * STAGEBYTES;
        uint32_t k0 = ps * BK;
#pragma unroll
        for (int i = 0; i < 2; i++) {
            CP_ASYNC16(base + a_dst[i],                 (const char*)(Ahi + a_src[i] + k0));
            CP_ASYNC16(base + TILEBYTES + a_dst[i],     (const char*)(Alo + a_src[i] + k0));
            CP_ASYNC16(base + 2 * TILEBYTES + a_dst[i], (const char*)(Bw  + b_src[i] + k0));
        }
        CP_COMMIT();
    }

    int slot = 0;
    for (int ch = 0; ch < nch; ch++) {
        // wait until stage `ch` is resident
        if (ch + 1 < nch) CP_WAIT(1); else CP_WAIT(0);
        __syncthreads();   // data visible to all; prior stage's reads complete

        // refill the stage freed last iteration with chunk ch+2
        if (ch + 2 < nch) {
            int ns = slot + 2; if (ns >= NSTAGE) ns -= NSTAGE;
            uint32_t base = sb + ns * STAGEBYTES;
            uint32_t k0 = (ch + 2) * BK;
#pragma unroll
            for (int i = 0; i < 2; i++) {
                CP_ASYNC16(base + a_dst[i],                 (const char*)(Ahi + a_src[i] + k0));
                CP_ASYNC16(base + TILEBYTES + a_dst[i],     (const char*)(Alo + a_src[i] + k0));
                CP_ASYNC16(base + 2 * TILEBYTES + a_dst[i], (const char*)(Bw  + b_src[i] + k0));
            }
            CP_COMMIT();
        }

        uint32_t Ahb = sb + slot * STAGEBYTES;
        uint32_t Alb = Ahb + TILEBYTES;
        uint32_t Bb  = Ahb + 2 * TILEBYTES;

#pragma unroll
        for (int ks = 0; ks < 2; ks++) {
            uint32_t kb = ks * 32;  // 16 fp16 = 32 bytes
            uint32_t Ah[4][4], Al[4][4], Bh[2][4];
#pragma unroll
            for (int m = 0; m < 4; m++) {
                LDSM_X4(Ah[m], Ahb + a_rel[m] + kb);
                LDSM_X4(Al[m], Alb + a_rel[m] + kb);
            }
#pragma unroll
            for (int p = 0; p < 2; p++)
                LDSM_X4(Bh[p], Bb + b_rel[p] + kb);
#pragma unroll
            for (int n = 0; n < 4; n++) {
                int p = n >> 1, q = (n & 1) * 2;
                uint32_t b0 = Bh[p][q], b1 = Bh[p][q + 1];
#pragma unroll
                for (int m = 0; m < 4; m++) {
                    MMA16816(acc[m][n], Ah[m], b0, b1);
                    MMA16816(acc[m][n], Al[m], b0, b1);
                }
            }
        }
        slot++; if (slot >= NSTAGE) slot = 0;
    }

    // ---- epilogue ----
    int g = lane >> 2, tig = lane & 3;
#pragma unroll
    for (int m = 0; m < 4; m++) {
        int lr = warp_m * 64 + m * 16 + g;
#pragma unroll
        for (int n = 0; n < 4; n++) {
            int col = n0 + warp_n * 32 + n * 8 + 2 * tig;
            float* c = acc[m][n];
#pragma unroll
            for (int h = 0; h < 2; h++) {
                int lrow = lr + h * 8;
                if (lrow >= mcount) continue;
                size_t grow = (size_t)(row0 + lrow);
                float f0 = c[h * 2 + 0], f1 = c[h * 2 + 1];
                if (applySilu) {
                    f0 = f0 / (1.f + expf(-f0));
                    f1 = f1 / (1.f + expf(-f1));
                    __half h0 = __float2half(f0);
                    __half h1 = __float2half(f1);
                    __half2 hv; hv.x = h0; hv.y = h1;
                    __half2 lv;
                    lv.x = __float2half(f0 - __half2float(h0));
                    lv.y = __float2half(f1 - __half2float(h1));
                    size_t idx = grow * Nd + col;
                    *reinterpret_cast<__half2*>(outHi + idx) = hv;
                    *reinterpret_cast<__half2*>(outLo + idx) = lv;
                } else {
                    float2 v; v.x = f0; v.y = f1;
                    *reinterpret_cast<float2*>(outF + grow * Nd + col) = v;
                }
            }
        }
    }
}

// ---------------- combine ----------------
__global__ void combine_kernel(float* __restrict__ out) {
    int token = blockIdx.x;
    int tid = threadIdx.x;
    int s0 = g_slot_of[token * 2 + 0];
    int s1 = g_slot_of[token * 2 + 1];
    float w0 = g_topw[token * 2 + 0];
    float w1 = g_topw[token * 2 + 1];
    const float4* y0 = (const float4*)(g_ybuf + (size_t)s0 * HIDDEN);
    const float4* y1 = (const float4*)(g_ybuf + (size_t)s1 * HIDDEN);
    float4* o = (float4*)(out + (size_t)token * HIDDEN);
    for (int h = tid; h < HIDDEN / 4; h += blockDim.x) {
        float4 a = y0[h], b = y1[h], r;
        r.x = w0 * a.x + w1 * b.x;
        r.y = w0 * a.y + w1 * b.y;
        r.z = w0 * a.z + w1 * b.z;
        r.w = w0 * a.w + w1 * b.w;
        o[h] = r;
    }
}

// ---------------- aux loss ----------------
__global__ void aux_kernel(float* __restrict__ out, int out_size) {
    if (threadIdx.x != 0 || blockIdx.x != 0) return;
    if (out_size <= NTOK * HIDDEN) return;
    float aux = 0.f;
    for (int e = 0; e < NEXP; e++)
        aux += ((float)g_cnt1[e] / (float)NTOK) * (g_probsum[e] / (float)NTOK);
    out[out_size - 1] = aux * (float)NEXP;
}

// ---------------- launch ----------------
extern "C" void kernel_launch(void* const* d_in, const int* in_sizes, int n_in,
                              void* d_out, int out_size) {
    const float* x  = (const float*)d_in[0];
    const float* wr = (const float*)d_in[1];
    const float* w1 = (const float*)d_in[2];
    const float* w2 = (const float*)d_in[3];
    float* out = (float*)d_out;

    static int configured = 0;
    if (!configured) {
        cudaFuncSetAttribute(moe_gemm, cudaFuncAttributeMaxDynamicSharedMemorySize, SMEM_TOTAL);
        configured = 1;
    }

    __half *xh, *xl, *w1t, *w2t, *hbh, *hbl;
    float* ybuf;
    cudaGetSymbolAddress((void**)&xh,  g_x_hi);
    cudaGetSymbolAddress((void**)&xl,  g_x_lo);
    cudaGetSymbolAddress((void**)&w1t, g_w1t);
    cudaGetSymbolAddress((void**)&w2t, g_w2t);
    cudaGetSymbolAddress((void**)&hbh, g_hb_hi);
    cudaGetSymbolAddress((void**)&hbl, g_hb_lo);
    cudaGetSymbolAddress((void**)&ybuf, g_ybuf);

    init_kernel<<<64, 256>>>();
    router_kernel<<<(NTOK * 32 + 255) / 256, 256>>>(x, wr);
    offsets_kernel<<<1, 32>>>();
    scatter_kernel<<<(SLOTS + 255) / 256, 256>>>();

    split_x_kernel<<<(NTOK * HIDDEN + 255) / 256, 256>>>(x);
    wconv_kernel<<<dim3(INTER / 32, HIDDEN / 32, NEXP), dim3(32, 8)>>>(w1, w1t, HIDDEN, INTER);
    wconv_kernel<<<dim3(HIDDEN / 32, INTER / 32, NEXP), dim3(32, 8)>>>(w2, w2t, INTER, HIDDEN);

    // GEMM1: hb[slot, INTER] = silu(gather(x) @ W1), fp16 hi/lo out
    moe_gemm<<<dim3(MAX_TILES, INTER / BN), 256, SMEM_TOTAL>>>(
        xh, xl, w1t, HIDDEN, INTER, 1, 1, hbh, hbl, (float*)0);
    // GEMM2: ybuf[slot, HIDDEN] = hb @ W2
    moe_gemm<<<dim3(MAX_TILES, HIDDEN / BN), 256, SMEM_TOTAL>>>(
        hbh, hbl, w2t, INTER, HIDDEN, 0, 0, (__half*)0, (__half*)0, ybuf);

    combine_kernel<<<NTOK, 256>>>(out);
    aux_kernel<<<1, 32>>>(out, out_size);
}

// round 8
// speedup vs baseline: 5.0866x; 1.4977x over previous
#include <cuda_runtime.h>
#include <cuda_fp16.h>
#include <math.h>
#include <stdint.h>

#define HIDDEN 1024
#define INTER  2048
#define NEXP   8
#define NTOK   8192
#define SLOTS  (NTOK * 2)          // 16384
#define BM 128
#define BN 128
#define BK 32
#define SLOTS_PAD (SLOTS + BM)
#define MAX_TILES (SLOTS / BM + NEXP)  // 136

#define STRIDE 80                  // padded smem row bytes (32 fp16 = 64B + 16B pad)
#define TILEBYTES (128 * STRIDE)   // 10240
#define STAGEBYTES (2 * TILEBYTES) // A, B = 20480
#define NSTAGE 3
#define SMEM_TOTAL (NSTAGE * STAGEBYTES)  // 61440

// ---------------- device scratch (static, no allocations) ----------------
__device__ int   g_cnt2[NEXP];
__device__ int   g_cnt1[NEXP];
__device__ float g_probsum[NEXP];
__device__ int   g_offset[NEXP + 1];
__device__ int   g_cursor[NEXP];
__device__ int   g_tile_e[MAX_TILES];
__device__ int   g_tile_row[MAX_TILES];
__device__ int   g_ntiles;
__device__ int   g_tok_list[SLOTS_PAD];
__device__ float g_slot_w[SLOTS_PAD];     // slot -> combine weight
__device__ float g_topw[SLOTS];
__device__ int   g_topi[SLOTS];

__device__ __half g_xh[NTOK * HIDDEN];
// W transposed to [E][N][K] K-major, fp16
__device__ __half g_w1t[NEXP * INTER * HIDDEN];
__device__ __half g_w2t[NEXP * HIDDEN * INTER];
// GEMM1 output (post-SiLU), fp16
__device__ __half g_hb[(size_t)SLOTS_PAD * INTER];

// ---------------- PTX helpers ----------------
__device__ __forceinline__ uint32_t smem_u32(const void* p) {
    uint32_t a;
    asm("{ .reg .u64 t; cvta.to.shared.u64 t, %1; cvt.u32.u64 %0, t; }" : "=r"(a) : "l"(p));
    return a;
}
#define CP_ASYNC16(dst, src) \
    asm volatile("cp.async.cg.shared.global [%0], [%1], 16;" :: "r"(dst), "l"(src) : "memory")
#define CP_COMMIT() asm volatile("cp.async.commit_group;" ::: "memory")
#define CP_WAIT(n)  asm volatile("cp.async.wait_group %0;" :: "n"(n) : "memory")

#define LDSM_X4(r, a) \
    asm volatile("ldmatrix.sync.aligned.m8n8.x4.shared.b16 {%0,%1,%2,%3}, [%4];" \
        : "=r"((r)[0]), "=r"((r)[1]), "=r"((r)[2]), "=r"((r)[3]) : "r"(a))

#define MMA16816(c, a, b0, b1) \
    asm volatile("mma.sync.aligned.m16n8k16.row.col.f32.f16.f16.f32 " \
        "{%0,%1,%2,%3}, {%4,%5,%6,%7}, {%8,%9}, {%0,%1,%2,%3};" \
        : "+f"((c)[0]), "+f"((c)[1]), "+f"((c)[2]), "+f"((c)[3]) \
        : "r"((a)[0]), "r"((a)[1]), "r"((a)[2]), "r"((a)[3]), "r"(b0), "r"(b1))

// ---------------- init ----------------
__global__ void init_kernel() {
    int i = blockIdx.x * blockDim.x + threadIdx.x;
    if (i < NEXP) { g_cnt1[i] = 0; g_cnt2[i] = 0; g_cursor[i] = 0; g_probsum[i] = 0.f; }
    for (int j = i; j < SLOTS_PAD; j += gridDim.x * blockDim.x) {
        g_tok_list[j] = 0;
        g_slot_w[j] = 0.f;
    }
}
// zero the output (atomics accumulate into it each replay)
__global__ void init_out_kernel(float* __restrict__ out) {
    int i = blockIdx.x * blockDim.x + threadIdx.x;
    float4 z; z.x = z.y = z.z = z.w = 0.f;
    for (int j = i; j < NTOK * HIDDEN / 4; j += gridDim.x * blockDim.x)
        ((float4*)out)[j] = z;
}

// ---------------- router: 1 warp per token ----------------
__global__ void router_kernel(const float* __restrict__ x, const float* __restrict__ wr) {
    int gwarp = (blockIdx.x * blockDim.x + threadIdx.x) >> 5;
    int lane = threadIdx.x & 31;
    if (gwarp >= NTOK) return;
    const float* xr = x + (size_t)gwarp * HIDDEN;
    float acc[NEXP];
#pragma unroll
    for (int e = 0; e < NEXP; e++) acc[e] = 0.f;
    for (int k = lane; k < HIDDEN; k += 32) {
        float xv = xr[k];
        const float* w = wr + (size_t)k * NEXP;
#pragma unroll
        for (int e = 0; e < NEXP; e++) acc[e] += xv * w[e];
    }
#pragma unroll
    for (int off = 16; off; off >>= 1)
#pragma unroll
        for (int e = 0; e < NEXP; e++) acc[e] += __shfl_xor_sync(0xffffffffu, acc[e], off);
    if (lane != 0) return;

    float mx = acc[0];
#pragma unroll
    for (int e = 1; e < NEXP; e++) mx = fmaxf(mx, acc[e]);
    float p[NEXP], s = 0.f;
#pragma unroll
    for (int e = 0; e < NEXP; e++) { p[e] = expf(acc[e] - mx); s += p[e]; }
    float inv = 1.f / s;
#pragma unroll
    for (int e = 0; e < NEXP; e++) p[e] *= inv;

    int i0 = 0; float v0 = p[0];
#pragma unroll
    for (int e = 1; e < NEXP; e++) if (p[e] > v0) { v0 = p[e]; i0 = e; }
    int i1 = -1; float v1 = -1.f;
#pragma unroll
    for (int e = 0; e < NEXP; e++) { if (e == i0) continue; if (p[e] > v1) { v1 = p[e]; i1 = e; } }
    float wsum = v0 + v1;
    g_topi[gwarp * 2 + 0] = i0; g_topw[gwarp * 2 + 0] = v0 / wsum;
    g_topi[gwarp * 2 + 1] = i1; g_topw[gwarp * 2 + 1] = v1 / wsum;
    atomicAdd(&g_cnt1[i0], 1);
    atomicAdd(&g_cnt2[i0], 1);
    atomicAdd(&g_cnt2[i1], 1);
#pragma unroll
    for (int e = 0; e < NEXP; e++) atomicAdd(&g_probsum[e], p[e]);
}

// ---------------- offsets + tile list ----------------
__global__ void offsets_kernel() {
    if (threadIdx.x != 0) return;
    int off = 0;
    for (int e = 0; e < NEXP; e++) { g_offset[e] = off; off += g_cnt2[e]; }
    g_offset[NEXP] = off;
    int idx = 0;
    for (int e = 0; e < NEXP; e++) {
        int nt = (g_cnt2[e] + BM - 1) / BM;
        int base = g_offset[e];
        for (int t = 0; t < nt; t++) { g_tile_e[idx] = e; g_tile_row[idx] = base + t * BM; idx++; }
    }
    g_ntiles = idx;
}

// ---------------- scatter ----------------
__global__ void scatter_kernel() {
    int i = blockIdx.x * blockDim.x + threadIdx.x;
    if (i >= SLOTS) return;
    int e = g_topi[i];
    int pos = atomicAdd(&g_cursor[e], 1);
    int slot = g_offset[e] + pos;
    g_tok_list[slot] = i >> 1;
    g_slot_w[slot] = g_topw[i];
}

// ---------------- x convert: f32 -> fp16 ----------------
__global__ void conv_x_kernel(const float* __restrict__ x) {
    int i = blockIdx.x * blockDim.x + threadIdx.x;
    if (i >= NTOK * HIDDEN / 2) return;
    float2 v = ((const float2*)x)[i];
    __half2 h; h.x = __float2half(v.x); h.y = __float2half(v.y);
    ((__half2*)g_xh)[i] = h;
}

// ---------------- W transpose + convert: [E][K][N] f32 -> [E][N][K] fp16 ----
__global__ void wconv_kernel(const float* __restrict__ W,
                             __half* __restrict__ out,
                             int K, int N) {
    __shared__ float t[32][33];
    int e = blockIdx.z;
    const float* Wb = W + (size_t)e * K * N;
    int n0 = blockIdx.x * 32, k0 = blockIdx.y * 32;
    for (int i = threadIdx.y; i < 32; i += 8)
        t[i][threadIdx.x] = Wb[(size_t)(k0 + i) * N + n0 + threadIdx.x];
    __syncthreads();
    for (int i = threadIdx.y; i < 32; i += 8) {
        float v = t[threadIdx.x][i];           // (k=k0+tx, n=n0+i)
        out[((size_t)e * N + n0 + i) * K + k0 + threadIdx.x] = __float2half(v);
    }
}

// ---------------- grouped fp16 mma.sync GEMM ----------------
// mode 0 (GEMM1): gathered A = x, SiLU, fp16 out to hb
// mode 1 (GEMM2): A = hb, epilogue fused combine: atomicAdd(out[token], w*val)
__global__ __launch_bounds__(256, 2)
void moe_gemm(const __half* __restrict__ A,
              const __half* __restrict__ Bw,
              int K, int Nd, int mode,
              __half* __restrict__ outH, float* __restrict__ outF) {
    int tile = blockIdx.x;
    if (tile >= g_ntiles) return;
    int e = g_tile_e[tile];
    int row0 = g_tile_row[tile];
    int mcount = g_offset[e + 1] - row0;
    if (mcount > BM) mcount = BM;
    int n0 = blockIdx.y * BN;

    extern __shared__ char smem[];
    uint32_t sb = smem_u32(smem);
    int tid = threadIdx.x;
    int lane = tid & 31;
    int wid = tid >> 5;
    int warp_m = wid & 1;        // 0..1 -> 64 rows each
    int warp_n = wid >> 1;       // 0..3 -> 32 cols each

    // ---- cp.async offsets (2 x 16B chunks per operand per thread) ----
    uint32_t a_src[2], a_dst[2], b_src[2];
#pragma unroll
    for (int i = 0; i < 2; i++) {
        int id = tid + i * 256;
        int row = id >> 2, c16 = id & 3;
        int srow = (mode == 0) ? g_tok_list[row0 + row] : (row0 + row);
        a_src[i] = (uint32_t)srow * (uint32_t)K + c16 * 8;
        a_dst[i] = row * STRIDE + c16 * 16;
        b_src[i] = ((uint32_t)e * (uint32_t)Nd + n0 + row) * (uint32_t)K + c16 * 8;
    }

    float acc[4][4][4];
#pragma unroll
    for (int m = 0; m < 4; m++)
#pragma unroll
        for (int n = 0; n < 4; n++)
#pragma unroll
            for (int r = 0; r < 4; r++) acc[m][n][r] = 0.f;

    // ldmatrix smem-relative offsets
    uint32_t a_rel[4], b_rel[2];
    {
        int row_a = warp_m * 64 + (lane & 15);
        int ka = ((lane >> 4) << 3) * 2;            // 0 or 16 bytes
#pragma unroll
        for (int m = 0; m < 4; m++) a_rel[m] = (row_a + m * 16) * STRIDE + ka;
        int row_b = warp_n * 32 + (lane & 7) + ((lane & 16) >> 1);
        int kb = (lane & 8) * 2;                    // 0 or 16 bytes
#pragma unroll
        for (int p = 0; p < 2; p++) b_rel[p] = (row_b + p * 16) * STRIDE + kb;
    }

    int nch = K / BK;

    // prologue: stages 0 and 1
#pragma unroll
    for (int ps = 0; ps < 2; ps++) {
        uint32_t base = sb + ps * STAGEBYTES;
        uint32_t k0 = ps * BK;
#pragma unroll
        for (int i = 0; i < 2; i++) {
            CP_ASYNC16(base + a_dst[i],             (const char*)(A  + a_src[i] + k0));
            CP_ASYNC16(base + TILEBYTES + a_dst[i], (const char*)(Bw + b_src[i] + k0));
        }
        CP_COMMIT();
    }

    int slot = 0;
    for (int ch = 0; ch < nch; ch++) {
        if (ch + 1 < nch) CP_WAIT(1); else CP_WAIT(0);
        __syncthreads();

        if (ch + 2 < nch) {
            int ns = slot + 2; if (ns >= NSTAGE) ns -= NSTAGE;
            uint32_t base = sb + ns * STAGEBYTES;
            uint32_t k0 = (ch + 2) * BK;
#pragma unroll
            for (int i = 0; i < 2; i++) {
                CP_ASYNC16(base + a_dst[i],             (const char*)(A  + a_src[i] + k0));
                CP_ASYNC16(base + TILEBYTES + a_dst[i], (const char*)(Bw + b_src[i] + k0));
            }
            CP_COMMIT();
        }

        uint32_t Ab = sb + slot * STAGEBYTES;
        uint32_t Bb = Ab + TILEBYTES;

#pragma unroll
        for (int ks = 0; ks < 2; ks++) {
            uint32_t kb = ks * 32;  // 16 fp16 = 32 bytes
            uint32_t Ar[4][4], Br[2][4];
#pragma unroll
            for (int m = 0; m < 4; m++)
                LDSM_X4(Ar[m], Ab + a_rel[m] + kb);
#pragma unroll
            for (int p = 0; p < 2; p++)
                LDSM_X4(Br[p], Bb + b_rel[p] + kb);
#pragma unroll
            for (int n = 0; n < 4; n++) {
                int p = n >> 1, q = (n & 1) * 2;
                uint32_t b0 = Br[p][q], b1 = Br[p][q + 1];
#pragma unroll
                for (int m = 0; m < 4; m++)
                    MMA16816(acc[m][n], Ar[m], b0, b1);
            }
        }
        slot++; if (slot >= NSTAGE) slot = 0;
    }

    // ---- epilogue ----
    int g = lane >> 2, tig = lane & 3;
    if (mode == 0) {
        // SiLU + fp16 store to hb
#pragma unroll
        for (int m = 0; m < 4; m++) {
            int lr = warp_m * 64 + m * 16 + g;
#pragma unroll
            for (int h = 0; h < 2; h++) {
                int lrow = lr + h * 8;
                if (lrow >= mcount) continue;
                size_t grow = (size_t)(row0 + lrow);
#pragma unroll
                for (int n = 0; n < 4; n++) {
                    int col = n0 + warp_n * 32 + n * 8 + 2 * tig;
                    float f0 = acc[m][n][h * 2 + 0];
                    float f1 = acc[m][n][h * 2 + 1];
                    f0 = f0 / (1.f + expf(-f0));
                    f1 = f1 / (1.f + expf(-f1));
                    __half2 hv; hv.x = __float2half(f0); hv.y = __float2half(f1);
                    *reinterpret_cast<__half2*>(outH + grow * Nd + col) = hv;
                }
            }
        }
    } else {
        // fused combine: out[token] += w * val (exactly 2 atomic adds per element)
#pragma unroll
        for (int m = 0; m < 4; m++) {
            int lr = warp_m * 64 + m * 16 + g;
#pragma unroll
            for (int h = 0; h < 2; h++) {
                int lrow = lr + h * 8;
                if (lrow >= mcount) continue;
                int srow = row0 + lrow;
                int token = g_tok_list[srow];
                float w = g_slot_w[srow];
                float* obase = outF + (size_t)token * HIDDEN;
#pragma unroll
                for (int n = 0; n < 4; n++) {
                    int col = n0 + warp_n * 32 + n * 8 + 2 * tig;
                    atomicAdd(obase + col,     w * acc[m][n][h * 2 + 0]);
                    atomicAdd(obase + col + 1, w * acc[m][n][h * 2 + 1]);
                }
            }
        }
    }
}

// ---------------- aux loss ----------------
__global__ void aux_kernel(float* __restrict__ out, int out_size) {
    if (threadIdx.x != 0 || blockIdx.x != 0) return;
    if (out_size <= NTOK * HIDDEN) return;
    float aux = 0.f;
    for (int e = 0; e < NEXP; e++)
        aux += ((float)g_cnt1[e] / (float)NTOK) * (g_probsum[e] / (float)NTOK);
    out[out_size - 1] = aux * (float)NEXP;
}

// ---------------- launch ----------------
extern "C" void kernel_launch(void* const* d_in, const int* in_sizes, int n_in,
                              void* d_out, int out_size) {
    const float* x  = (const float*)d_in[0];
    const float* wr = (const float*)d_in[1];
    const float* w1 = (const float*)d_in[2];
    const float* w2 = (const float*)d_in[3];
    float* out = (float*)d_out;

    static int configured = 0;
    if (!configured) {
        cudaFuncSetAttribute(moe_gemm, cudaFuncAttributeMaxDynamicSharedMemorySize, SMEM_TOTAL);
        configured = 1;
    }

    __half *xh, *w1t, *w2t, *hb;
    cudaGetSymbolAddress((void**)&xh,  g_xh);
    cudaGetSymbolAddress((void**)&w1t, g_w1t);
    cudaGetSymbolAddress((void**)&w2t, g_w2t);
    cudaGetSymbolAddress((void**)&hb,  g_hb);

    init_kernel<<<64, 256>>>();
    init_out_kernel<<<296, 256>>>(out);
    router_kernel<<<(NTOK * 32 + 255) / 256, 256>>>(x, wr);
    offsets_kernel<<<1, 32>>>();
    scatter_kernel<<<(SLOTS + 255) / 256, 256>>>();

    conv_x_kernel<<<(NTOK * HIDDEN / 2 + 255) / 256, 256>>>(x);
    wconv_kernel<<<dim3(INTER / 32, HIDDEN / 32, NEXP), dim3(32, 8)>>>(w1, w1t, HIDDEN, INTER);
    wconv_kernel<<<dim3(HIDDEN / 32, INTER / 32, NEXP), dim3(32, 8)>>>(w2, w2t, INTER, HIDDEN);

    // GEMM1: hb[slot, INTER] = silu(gather(x) @ W1), fp16
    moe_gemm<<<dim3(MAX_TILES, INTER / BN), 256, SMEM_TOTAL>>>(
        xh, w1t, HIDDEN, INTER, 0, hb, (float*)0);
    // GEMM2 + fused combine: out[token] += w * (hb @ W2)
    moe_gemm<<<dim3(MAX_TILES, HIDDEN / BN), 256, SMEM_TOTAL>>>(
        hb, w2t, INTER, HIDDEN, 1, (__half*)0, out);

    aux_kernel<<<1, 32>>>(out, out_size);
}